// round 6
// baseline (speedup 1.0000x reference)
#include <cuda_runtime.h>
#include <cuda_bf16.h>
#include <cstdint>

// ---------------- problem constants ----------------
#define T_TOK 8192
#define DIN   4096
#define DOUT  4096
#define CL    256                  // NUM_ADAPTERS * MAX_RANK pages
#define KSEG  (DIN + CL)           // 4352 (one split segment: x | xa)
#define KSTRIDE (2 * KSEG)         // 8704 packed row stride (hi | lo)
#define BK    32
#define SEG_CH (KSEG / BK)         // 136 chunks per segment
#define KCH   (3 * SEG_CH)         // 408 logical chunks (3 split terms)

#define SSTRIDE 40                 // smem row stride in bf16 (80B: conflict-free ldmatrix)
#define ATILE_B (128 * SSTRIDE * 2)       // 10240 B per A (or B) stage tile
#define STAGE_B (2 * ATILE_B)             // 20480 B per pipeline stage
#define NSTAGE  3
#define DSMEM_B (NSTAGE * STAGE_B)        // 61440 B dynamic smem

// ---------------- device scratch (no allocs allowed; zero-initialized) ----------------
// A2 row t: [x_hi(4096) | xa_hi(256) | x_lo(4096) | xa_lo(256)]
__device__ __nv_bfloat16 g_A2[(size_t)T_TOK * KSTRIDE];
// B2 row n: [W_hi | BT_hi | W_lo | BT_lo]
__device__ __nv_bfloat16 g_B2[(size_t)DOUT * KSTRIDE];
// B1 row j: [Acat_hi | 0(256) | Acat_lo | 0(256)]   (zero slots never written)
__device__ __nv_bfloat16 g_B1[(size_t)CL * KSTRIDE];
// gemm1 output (fp32): routed low-rank activations
__device__ float g_xa[(size_t)T_TOK * CL];

// ---------------- generic-PTX helpers (sm_80+ features only) ----------------
__device__ __forceinline__ uint32_t smem_u32(const void* p) {
    uint32_t a;
    asm("{ .reg .u64 t; cvta.to.shared.u64 t, %1; cvt.u32.u64 %0, t; }" : "=r"(a) : "l"(p));
    return a;
}
__device__ __forceinline__ void cp_async16(uint32_t saddr, const void* gaddr) {
    asm volatile("cp.async.cg.shared.global [%0], [%1], 16;" :: "r"(saddr), "l"(gaddr));
}
__device__ __forceinline__ void cp_commit() { asm volatile("cp.async.commit_group;"); }
__device__ __forceinline__ void cp_wait1()  { asm volatile("cp.async.wait_group 1;" ::: "memory"); }
__device__ __forceinline__ void cp_wait0()  { asm volatile("cp.async.wait_group 0;" ::: "memory"); }

__device__ __forceinline__ void ldm_x4(uint32_t* r, uint32_t addr) {
    asm volatile("ldmatrix.sync.aligned.m8n8.x4.shared.b16 {%0,%1,%2,%3}, [%4];"
                 : "=r"(r[0]), "=r"(r[1]), "=r"(r[2]), "=r"(r[3]) : "r"(addr));
}
__device__ __forceinline__ void ldm_x2(uint32_t* r, uint32_t addr) {
    asm volatile("ldmatrix.sync.aligned.m8n8.x2.shared.b16 {%0,%1}, [%2];"
                 : "=r"(r[0]), "=r"(r[1]) : "r"(addr));
}
__device__ __forceinline__ void mma16816(float* c, const uint32_t* a, const uint32_t* b) {
    asm volatile(
        "mma.sync.aligned.m16n8k16.row.col.f32.bf16.bf16.f32 "
        "{%0,%1,%2,%3}, {%4,%5,%6,%7}, {%8,%9}, {%0,%1,%2,%3};"
        : "+f"(c[0]), "+f"(c[1]), "+f"(c[2]), "+f"(c[3])
        : "r"(a[0]), "r"(a[1]), "r"(a[2]), "r"(a[3]), "r"(b[0]), "r"(b[1]));
}

// ---------------- split helpers ----------------
__device__ __forceinline__ void split2(float v, __nv_bfloat16& hi, __nv_bfloat16& lo) {
    hi = __float2bfloat16(v);
    lo = __float2bfloat16(v - __bfloat162float(hi));
}

// ---------------- packing kernels ----------------
__global__ void pack_x(const float* __restrict__ x) {
    size_t i4 = ((size_t)blockIdx.x * blockDim.x + threadIdx.x) * 4;
    size_t t = i4 / DIN, k = i4 % DIN;
    float4 v = *(const float4*)(x + i4);
    __nv_bfloat16 h[4], l[4];
    split2(v.x, h[0], l[0]); split2(v.y, h[1], l[1]);
    split2(v.z, h[2], l[2]); split2(v.w, h[3], l[3]);
    __nv_bfloat16* row = g_A2 + t * KSTRIDE;
#pragma unroll
    for (int q = 0; q < 4; ++q) {
        row[k + q] = h[q];
        row[KSEG + k + q] = l[q];
    }
}
__global__ void pack_w(const float* __restrict__ w) {
    size_t i4 = ((size_t)blockIdx.x * blockDim.x + threadIdx.x) * 4;
    size_t n = i4 / DIN, k = i4 % DIN;
    float4 v = *(const float4*)(w + i4);
    __nv_bfloat16 h[4], l[4];
    split2(v.x, h[0], l[0]); split2(v.y, h[1], l[1]);
    split2(v.z, h[2], l[2]); split2(v.w, h[3], l[3]);
    __nv_bfloat16* row = g_B2 + n * KSTRIDE;
#pragma unroll
    for (int q = 0; q < 4; ++q) {
        row[k + q] = h[q];
        row[KSEG + k + q] = l[q];
    }
}
__global__ void pack_bt(const float* __restrict__ b_cache, const int* __restrict__ page) {
    size_t idx = (size_t)blockIdx.x * blockDim.x + threadIdx.x;   // DOUT*CL threads
    size_t n = idx / CL, j = idx % CL;
    float v = b_cache[(size_t)page[j] * DOUT + n];
    __nv_bfloat16 hi, lo;
    split2(v, hi, lo);
    __nv_bfloat16* row = g_B2 + n * KSTRIDE;
    row[DIN + j] = hi;
    row[KSEG + DIN + j] = lo;
}
__global__ void pack_b1(const float* __restrict__ a_cache, const int* __restrict__ page,
                        const int* __restrict__ ranks) {
    size_t i4 = ((size_t)blockIdx.x * blockDim.x + threadIdx.x) * 4;
    size_t j = i4 / DIN, k = i4 % DIN;
    int a = (int)(j >> 6), r = (int)(j & 63);
    float am = (r < ranks[a]) ? 1.0f : 0.0f;
    float4 v = *(const float4*)(a_cache + (size_t)page[j] * DIN + k);
    v.x *= am; v.y *= am; v.z *= am; v.w *= am;
    __nv_bfloat16 h[4], l[4];
    split2(v.x, h[0], l[0]); split2(v.y, h[1], l[1]);
    split2(v.z, h[2], l[2]); split2(v.w, h[3], l[3]);
    __nv_bfloat16* row = g_B1 + j * KSTRIDE;
#pragma unroll
    for (int q = 0; q < 4; ++q) {
        row[k + q] = h[q];
        row[KSEG + k + q] = l[q];
    }
}
__global__ void pack_xa() {
    size_t i4 = ((size_t)blockIdx.x * blockDim.x + threadIdx.x) * 4;
    size_t t = i4 / CL, j = i4 % CL;
    float4 v = *(const float4*)(g_xa + i4);
    __nv_bfloat16 h[4], l[4];
    split2(v.x, h[0], l[0]); split2(v.y, h[1], l[1]);
    split2(v.z, h[2], l[2]); split2(v.w, h[3], l[3]);
    __nv_bfloat16* row = g_A2 + t * KSTRIDE;
#pragma unroll
    for (int q = 0; q < 4; ++q) {
        row[DIN + j + q] = h[q];
        row[KSEG + DIN + j + q] = l[q];
    }
}

// ---------------- mma.sync GEMM: C[M,N] = sum over 3 split terms ----------------
// CTA 128x128, BK=32, 8 warps (2x4), warp tile 64x32, m16n8k16 bf16 -> fp32.
// 3-stage cp.async pipeline with ARITHMETIC stage addressing (no runtime-indexed
// arrays -> no local-memory spill in the hot loop).
// Per-chunk K map: term0 (A hi, B hi), term1 (A lo, B hi), term2 (A hi, B lo).
// MASK=true: gemm1 (adapter mask); false: gemm2 (+bias).
template <bool MASK>
__global__ __launch_bounds__(256, 2)
void mma_gemm(const __nv_bfloat16* __restrict__ A,
              const __nv_bfloat16* __restrict__ B,
              const float* __restrict__ bias,
              const int* __restrict__ adapter_ids,
              float* __restrict__ C, int ldc)
{
    extern __shared__ char dsm[];

    const int tid  = threadIdx.x;
    const int lane = tid & 31;
    const int wid  = tid >> 5;
    const int wm   = wid >> 2;          // 0..1 -> warp row (64 rows)
    const int wn   = wid & 3;           // 0..3 -> warp col (32 cols)
    const int bm   = blockIdx.y * 128;
    const int bn   = blockIdx.x * 128;

    // ---- cp.async tile-fill maps: 512 16B-units per tile, 2 per thread ----
    const int u0 = tid, u1 = tid + 256;
    const int r0 = u0 >> 2, n0u = u0 & 3;
    const int r1 = u1 >> 2, n1u = u1 & 3;

    const __nv_bfloat16* Ag0 = A + (size_t)(bm + r0) * KSTRIDE + n0u * 8;
    const __nv_bfloat16* Ag1 = A + (size_t)(bm + r1) * KSTRIDE + n1u * 8;
    const __nv_bfloat16* Bg0 = B + (size_t)(bn + r0) * KSTRIDE + n0u * 8;
    const __nv_bfloat16* Bg1 = B + (size_t)(bn + r1) * KSTRIDE + n1u * 8;

    // Per-thread byte offsets (stage-independent); stage base added arithmetically.
    const uint32_t dbase  = smem_u32(dsm);
    const uint32_t offA0  = (r0 * SSTRIDE + n0u * 8) * 2;
    const uint32_t offA1  = (r1 * SSTRIDE + n1u * 8) * 2;
    const uint32_t offB0  = ATILE_B + (r0 * SSTRIDE + n0u * 8) * 2;
    const uint32_t offB1  = ATILE_B + (r1 * SSTRIDE + n1u * 8) * 2;
    // ldmatrix bases: A x4 row = wm*64 + (lane&15), col8 = lane>>4
    //                 B x2 row = wn*32 + (lane&7),  col8 = (lane>>3)&1
    const uint32_t aOff = ((wm * 64 + (lane & 15)) * SSTRIDE + (lane >> 4) * 8) * 2;
    const uint32_t bOff = ATILE_B + ((wn * 32 + (lane & 7)) * SSTRIDE + ((lane >> 3) & 1) * 8) * 2;

    float acc[4][4][4];
#pragma unroll
    for (int mi = 0; mi < 4; ++mi)
#pragma unroll
        for (int ni = 0; ni < 4; ++ni)
#pragma unroll
            for (int q = 0; q < 4; ++q) acc[mi][ni][q] = 0.0f;

    // chunk -> packed K offsets (elements). term0: A hi / B hi; term1: A lo / B hi;
    // term2: A hi / B lo.
    auto issue_loads = [&](int c, int s) {
        const uint32_t st = dbase + (uint32_t)s * STAGE_B;
        const size_t ka = (size_t)((c < 2 * SEG_CH) ? c : c - 2 * SEG_CH) * BK;
        const size_t kb = (size_t)((c < SEG_CH) ? c : c - SEG_CH) * BK;
        cp_async16(st + offA0, Ag0 + ka);
        cp_async16(st + offA1, Ag1 + ka);
        cp_async16(st + offB0, Bg0 + kb);
        cp_async16(st + offB1, Bg1 + kb);
        cp_commit();
    };

    // prologue: stages 0,1 in flight
    issue_loads(0, 0);
    issue_loads(1, 1);

    int s = 0;                       // stage of chunk c (incremented mod 3)
    int s2 = 2;                      // stage of chunk c+2
    for (int c = 0; c < KCH; ++c) {
        if (c + 2 < KCH) cp_wait1(); else cp_wait0();
        __syncthreads();
        if (c + 2 < KCH) issue_loads(c + 2, s2);

        const uint32_t st = dbase + (uint32_t)s * STAGE_B;
        const uint32_t aB = st + aOff;
        const uint32_t bB = st + bOff;
#pragma unroll
        for (int ks = 0; ks < 2; ++ks) {
            uint32_t a[4][4], b[4][2];
#pragma unroll
            for (int mi = 0; mi < 4; ++mi)
                ldm_x4(a[mi], aB + (mi * 16 * SSTRIDE + ks * 16) * 2);
#pragma unroll
            for (int ni = 0; ni < 4; ++ni)
                ldm_x2(b[ni], bB + (ni * 8 * SSTRIDE + ks * 16) * 2);
#pragma unroll
            for (int mi = 0; mi < 4; ++mi)
#pragma unroll
                for (int ni = 0; ni < 4; ++ni)
                    mma16816(acc[mi][ni], a[mi], b[ni]);
        }

        s  = (s  == NSTAGE - 1) ? 0 : s  + 1;
        s2 = (s2 == NSTAGE - 1) ? 0 : s2 + 1;
    }

    // ---- epilogue ----
    const int trow = lane >> 2, tcol = (lane & 3) * 2;
#pragma unroll
    for (int mi = 0; mi < 4; ++mi) {
        const int mA = bm + wm * 64 + mi * 16 + trow;
        const int mB = mA + 8;
        int aidA = 0, aidB = 0;
        if (MASK) { aidA = adapter_ids[mA]; aidB = adapter_ids[mB]; }
#pragma unroll
        for (int ni = 0; ni < 4; ++ni) {
            const int n = bn + wn * 32 + ni * 8 + tcol;
            float2 vA = make_float2(acc[mi][ni][0], acc[mi][ni][1]);
            float2 vB = make_float2(acc[mi][ni][2], acc[mi][ni][3]);
            if (MASK) {
                const int slot = n >> 6;          // n, n+1 share the slot (n even)
                if (slot != aidA) { vA.x = 0.0f; vA.y = 0.0f; }
                if (slot != aidB) { vB.x = 0.0f; vB.y = 0.0f; }
            } else {
                const float2 bz = *(const float2*)(bias + n);
                vA.x += bz.x; vA.y += bz.y;
                vB.x += bz.x; vB.y += bz.y;
            }
            *(float2*)(C + (size_t)mA * ldc + n) = vA;
            *(float2*)(C + (size_t)mB * ldc + n) = vB;
        }
    }
}

// ---------------- launch ----------------
extern "C" void kernel_launch(void* const* d_in, const int* in_sizes, int n_in,
                              void* d_out, int out_size)
{
    const float* x           = (const float*)d_in[0];
    const float* w           = (const float*)d_in[1];
    const float* bias        = (const float*)d_in[2];
    const float* a_cache     = (const float*)d_in[3];
    const float* b_cache     = (const float*)d_in[4];
    const int*   adapter_ids = (const int*)d_in[5];
    const int*   page        = (const int*)d_in[6];
    const int*   ranks       = (const int*)d_in[7];
    float*       out         = (float*)d_out;

    __nv_bfloat16 *pA2, *pB2, *pB1;
    float* pxa;
    cudaGetSymbolAddress((void**)&pA2, g_A2);
    cudaGetSymbolAddress((void**)&pB2, g_B2);
    cudaGetSymbolAddress((void**)&pB1, g_B1);
    cudaGetSymbolAddress((void**)&pxa, g_xa);

    cudaFuncSetAttribute(mma_gemm<true>,
                         cudaFuncAttributeMaxDynamicSharedMemorySize, DSMEM_B);
    cudaFuncSetAttribute(mma_gemm<false>,
                         cudaFuncAttributeMaxDynamicSharedMemorySize, DSMEM_B);

    // pack operands (bf16 hi/lo splits, gathers)
    pack_x <<<(T_TOK * DIN) / 4 / 256, 256>>>(x);
    pack_w <<<(DOUT * DIN) / 4 / 256, 256>>>(w);
    pack_bt<<<(DOUT * CL)      / 256, 256>>>(b_cache, page);
    pack_b1<<<(CL * DIN)   / 4 / 256, 256>>>(a_cache, page, ranks);

    // gemm1: g_xa[8192,256] = adapter-mask(x @ Acat^T)  (xa slots hit zero B1 cols)
    mma_gemm<true><<<dim3(CL / 128, T_TOK / 128), 256, DSMEM_B>>>(
        pA2, pB1, nullptr, adapter_ids, pxa, CL);

    // insert xa splits into A2
    pack_xa<<<(T_TOK * CL) / 4 / 256, 256>>>();

    // gemm2: out = x @ W^T + xa @ BT^T + bias  (3-term split, fused LoRA K-extension)
    mma_gemm<false><<<dim3(DOUT / 128, T_TOK / 128), 256, DSMEM_B>>>(
        pA2, pB2, bias, nullptr, out, DOUT);
}